// round 4
// baseline (speedup 1.0000x reference)
#include <cuda_runtime.h>
#include <cstdint>
#include <cstddef>

// ---------------- problem constants ----------------
#define B_     64
#define NKV    8192
#define D      64      // INPUT_SIZE == SLOT_SIZE
#define NQ     8
#define C32    32      // NUM_HEADS * NUM_SLOTS
#define EPS_A  1e-8f
#define NCHUNK 8
#define TPC    1024    // tokens per CTA
#define TT     128     // tokens per tile
#define NTILES (TPC / TT)   // 8

#define SX  68         // smem row stride for lnX tile [128][SX]
#define SAT 132        // smem row stride for attn^T   [32][SAT]
#define SWF 68         // smem row stride for Wfold    [32][SWF]

// ---------------- device scratch (no allocs allowed) ----------------
__device__ float g_wfold[B_ * C32 * D];              // [b][c][e], tf32-rounded
__device__ float g_part [B_ * NCHUNK * C32 * D];     // per-chunk S' partials
__device__ float g_sap  [B_ * NCHUNK * C32];         // per-chunk column-sum partials
__device__ float g_slots[B_ * NQ * D];               // working slots

// ---------------- helpers ----------------
__device__ __forceinline__ float to_tf32(float x) {
    uint32_t u;
    asm("cvt.rna.tf32.f32 %0, %1;" : "=r"(u) : "f"(x));
    return __uint_as_float(u);
}
__device__ __forceinline__ uint32_t f2u(float x) { return __float_as_uint(x); }

__device__ __forceinline__ void mma8(float c[4],
                                     uint32_t a0, uint32_t a1, uint32_t a2, uint32_t a3,
                                     uint32_t b0, uint32_t b1) {
    asm volatile(
        "mma.sync.aligned.m16n8k8.row.col.f32.tf32.tf32.f32 "
        "{%0,%1,%2,%3},{%4,%5,%6,%7},{%8,%9},{%0,%1,%2,%3};"
        : "+f"(c[0]), "+f"(c[1]), "+f"(c[2]), "+f"(c[3])
        : "r"(a0), "r"(a1), "r"(a2), "r"(a3), "r"(b0), "r"(b1));
}

__device__ __forceinline__ void cp_async16(uint32_t smem_addr, const void* gptr) {
    asm volatile("cp.async.cg.shared.global [%0], [%1], 16;"
                 :: "r"(smem_addr), "l"(gptr));
}
__device__ __forceinline__ void cp_commit() {
    asm volatile("cp.async.commit_group;");
}
__device__ __forceinline__ void cp_wait0() {
    asm volatile("cp.async.wait_group 0;");
}

// =====================================================================
// Main fused streaming kernel: one CTA per (batch, 1024-token chunk),
// eight 128-token tiles, cp.async double-buffered across tiles.
// =====================================================================
__global__ void __launch_bounds__(256, 2)
vslot_main(const float* __restrict__ inputs,
           const float* __restrict__ lng_g,
           const float* __restrict__ lnb_g,
           float* __restrict__ vis,
           int last)
{
    extern __shared__ float sm[];
    float* sx0  = sm;                      // [128][SX] tile buffer 0
    float* sx1  = sx0 + TT * SX;           // [128][SX] tile buffer 1
    float* sat  = sx1 + TT * SX;           // [32][SAT] (attn+eps)^T (tf32)
    float* swf  = sat + C32 * SAT;         // [32][SWF] Wfold[c][e]
    float* slng = swf + C32 * SWF;         // [64]
    float* slnb = slng + 64;               // [64]

    const int b     = blockIdx.x >> 3;
    const int chunk = blockIdx.x & 7;
    const int n0    = chunk * TPC;
    const int tid   = threadIdx.x;
    const int w     = tid >> 5;
    const int lane  = tid & 31;
    const int g     = lane >> 2;   // groupID  (0..7)
    const int t     = lane & 3;    // threadID_in_group (0..3)
    const int r0    = w * 16 + g;  // this thread's mma row (and r0+8)

    for (int i = tid; i < C32 * D; i += 256)
        swf[(i >> 6) * SWF + (i & 63)] = g_wfold[b * C32 * D + i];
    if (tid < 64) { slng[tid] = lng_g[tid]; slnb[tid] = lnb_g[tid]; }

    const float4* gbase = reinterpret_cast<const float4*>(
        inputs + ((size_t)b * NKV + n0) * D);
    uint32_t sxa[2];
    sxa[0] = (uint32_t)__cvta_generic_to_shared(sx0);
    sxa[1] = (uint32_t)__cvta_generic_to_shared(sx1);

    // prologue: prefetch tile 0 into buffer 0
    #pragma unroll
    for (int k = 0; k < 8; k++) {
        int i = tid + 256 * k;
        cp_async16(sxa[0] + ((i >> 4) * SX + (i & 15) * 4) * 4, gbase + i);
    }
    cp_commit();

    float c2[2][4];        // GEMM2 accumulators (persist across tiles)
    float colsum[4][2];    // per-owned-column (attn+eps) sums
    #pragma unroll
    for (int a = 0; a < 2; a++)
        #pragma unroll
        for (int i = 0; i < 4; i++) c2[a][i] = 0.f;
    #pragma unroll
    for (int a = 0; a < 4; a++) { colsum[a][0] = 0.f; colsum[a][1] = 0.f; }

    #pragma unroll 1
    for (int t4 = 0; t4 < NTILES; t4++) {
        float* sx = (t4 & 1) ? sx1 : sx0;

        cp_wait0();
        __syncthreads();   // tile t4 visible; all warps done reading buf(t4^1)

        if (t4 + 1 < NTILES) {   // prefetch next tile into the other buffer
            const float4* gn = gbase + (size_t)(t4 + 1) * (TT * D / 4);
            uint32_t dst = sxa[(t4 + 1) & 1];
            #pragma unroll
            for (int k = 0; k < 8; k++) {
                int i = tid + 256 * k;
                cp_async16(dst + ((i >> 4) * SX + (i & 15) * 4) * 4, gn + i);
            }
            cp_commit();
        }

        // ---- layernorm in A-fragment layout: rows r0, r0+8, cols 4j+t ----
        float v0[16], v1[16];
        float s0 = 0.f, q0 = 0.f, s1 = 0.f, q1 = 0.f;
        {
            const float* p0 = &sx[r0 * SX + t];
            const float* p1 = &sx[(r0 + 8) * SX + t];
            #pragma unroll
            for (int j = 0; j < 16; j++) {
                float x0 = p0[4 * j], x1 = p1[4 * j];
                v0[j] = x0; v1[j] = x1;
                s0 += x0; q0 = fmaf(x0, x0, q0);
                s1 += x1; q1 = fmaf(x1, x1, q1);
            }
            s0 += __shfl_xor_sync(0xffffffffu, s0, 1);
            q0 += __shfl_xor_sync(0xffffffffu, q0, 1);
            s1 += __shfl_xor_sync(0xffffffffu, s1, 1);
            q1 += __shfl_xor_sync(0xffffffffu, q1, 1);
            s0 += __shfl_xor_sync(0xffffffffu, s0, 2);
            q0 += __shfl_xor_sync(0xffffffffu, q0, 2);
            s1 += __shfl_xor_sync(0xffffffffu, s1, 2);
            q1 += __shfl_xor_sync(0xffffffffu, q1, 2);
            float m0 = s0 * (1.f / 64.f);
            float m1 = s1 * (1.f / 64.f);
            float rs0 = rsqrtf(fmaf(-m0, m0, q0 * (1.f / 64.f)) + 1e-5f);
            float rs1 = rsqrtf(fmaf(-m1, m1, q1 * (1.f / 64.f)) + 1e-5f);
            float* o0 = &sx[r0 * SX + t];
            float* o1 = &sx[(r0 + 8) * SX + t];
            #pragma unroll
            for (int j = 0; j < 16; j++) {
                float gg = slng[4 * j + t], bb = slnb[4 * j + t];
                v0[j] = to_tf32(fmaf((v0[j] - m0) * rs0, gg, bb));
                v1[j] = to_tf32(fmaf((v1[j] - m1) * rs1, gg, bb));
                o0[4 * j] = v0[j];
                o1[4 * j] = v1[j];
            }
        }

        // ---- GEMM1: logits[128,32] = lnX @ Wfold, A from registers ----
        float c1[4][4];
        #pragma unroll
        for (int j = 0; j < 4; j++)
            #pragma unroll
            for (int i = 0; i < 4; i++) c1[j][i] = 0.f;
        #pragma unroll
        for (int ks = 0; ks < 8; ks++) {
            uint32_t a0 = f2u(v0[2 * ks]);
            uint32_t a1 = f2u(v1[2 * ks]);
            uint32_t a2 = f2u(v0[2 * ks + 1]);
            uint32_t a3 = f2u(v1[2 * ks + 1]);
            #pragma unroll
            for (int j = 0; j < 4; j++) {
                const float* bp = &swf[(8 * j + g) * SWF + 8 * ks + t];
                mma8(c1[j], a0, a1, a2, a3, f2u(bp[0]), f2u(bp[4]));
            }
        }

        // ---- softmax over 32 cols for rows r0, r0+8 ----
        float m0 = -1e30f, m1 = -1e30f;
        #pragma unroll
        for (int j = 0; j < 4; j++) {
            m0 = fmaxf(m0, fmaxf(c1[j][0], c1[j][1]));
            m1 = fmaxf(m1, fmaxf(c1[j][2], c1[j][3]));
        }
        m0 = fmaxf(m0, __shfl_xor_sync(0xffffffffu, m0, 1));
        m0 = fmaxf(m0, __shfl_xor_sync(0xffffffffu, m0, 2));
        m1 = fmaxf(m1, __shfl_xor_sync(0xffffffffu, m1, 1));
        m1 = fmaxf(m1, __shfl_xor_sync(0xffffffffu, m1, 2));
        float ss0 = 0.f, ss1 = 0.f;
        #pragma unroll
        for (int j = 0; j < 4; j++) {
            c1[j][0] = __expf(c1[j][0] - m0);
            c1[j][1] = __expf(c1[j][1] - m0);
            c1[j][2] = __expf(c1[j][2] - m1);
            c1[j][3] = __expf(c1[j][3] - m1);
            ss0 += c1[j][0] + c1[j][1];
            ss1 += c1[j][2] + c1[j][3];
        }
        ss0 += __shfl_xor_sync(0xffffffffu, ss0, 1);
        ss0 += __shfl_xor_sync(0xffffffffu, ss0, 2);
        ss1 += __shfl_xor_sync(0xffffffffu, ss1, 1);
        ss1 += __shfl_xor_sync(0xffffffffu, ss1, 2);
        float inv0 = 1.f / ss0, inv1 = 1.f / ss1;

        if (last) {   // attn_vis[b,n,q] = sum_h attn[n, h*8+q]
            float w00 = 0.f, w01 = 0.f, w10 = 0.f, w11 = 0.f;
            #pragma unroll
            for (int j = 0; j < 4; j++) {
                w00 += c1[j][0]; w01 += c1[j][1];
                w10 += c1[j][2]; w11 += c1[j][3];
            }
            size_t nrow = (size_t)b * NKV + n0 + t4 * TT;
            *reinterpret_cast<float2*>(&vis[(nrow + r0) * NQ + 2 * t])
                = make_float2(w00 * inv0, w01 * inv0);
            *reinterpret_cast<float2*>(&vis[(nrow + r0 + 8) * NQ + 2 * t])
                = make_float2(w10 * inv1, w11 * inv1);
        }

        // ---- attn+eps -> sat (transposed, tf32) + column sums ----
        #pragma unroll
        for (int j = 0; j < 4; j++) {
            int cc = 8 * j + 2 * t;
            float a00 = fmaf(c1[j][0], inv0, EPS_A);
            float a01 = fmaf(c1[j][1], inv0, EPS_A);
            float a10 = fmaf(c1[j][2], inv1, EPS_A);
            float a11 = fmaf(c1[j][3], inv1, EPS_A);
            sat[cc * SAT + r0]           = to_tf32(a00);
            sat[(cc + 1) * SAT + r0]     = to_tf32(a01);
            sat[cc * SAT + r0 + 8]       = to_tf32(a10);
            sat[(cc + 1) * SAT + r0 + 8] = to_tf32(a11);
            colsum[j][0] += a00 + a10;
            colsum[j][1] += a01 + a11;
        }
        __syncthreads();   // sat + tf32 lnX visible to all warps

        // ---- GEMM2: S'[32,64] += (attn+eps)^T[32,128] @ lnX[128,64] ----
        {
            const int mblk = w >> 2;          // 0..1
            const int ncol = (w & 3) * 16;    // 16 output cols per warp
            const float* atp = &sat[(16 * mblk + g) * SAT];
            #pragma unroll
            for (int ks = 0; ks < 16; ks++) {
                int kb = 8 * ks;
                uint32_t a0 = f2u(atp[kb + t]);
                uint32_t a1 = f2u(atp[8 * SAT + kb + t]);
                uint32_t a2 = f2u(atp[kb + t + 4]);
                uint32_t a3 = f2u(atp[8 * SAT + kb + t + 4]);
                #pragma unroll
                for (int nb = 0; nb < 2; nb++) {
                    const float* bp = &sx[(kb + t) * SX + ncol + 8 * nb + g];
                    mma8(c2[nb], a0, a1, a2, a3, f2u(bp[0]), f2u(bp[4 * SX]));
                }
            }
        }
    }

    // ---- epilogue: deterministic per-chunk partials ----
    {
        const int mblk = w >> 2;
        const int ncol = (w & 3) * 16;
        const int crow = 16 * mblk + g;
        float* pp = &g_part[(size_t)(b * NCHUNK + chunk) * C32 * D];
        #pragma unroll
        for (int nb = 0; nb < 2; nb++) {
            int e0 = ncol + 8 * nb + 2 * t;
            pp[crow * D + e0]           = c2[nb][0];
            pp[crow * D + e0 + 1]       = c2[nb][1];
            pp[(crow + 8) * D + e0]     = c2[nb][2];
            pp[(crow + 8) * D + e0 + 1] = c2[nb][3];
        }
        #pragma unroll
        for (int off = 4; off < 32; off <<= 1) {
            #pragma unroll
            for (int j = 0; j < 4; j++) {
                colsum[j][0] += __shfl_xor_sync(0xffffffffu, colsum[j][0], off);
                colsum[j][1] += __shfl_xor_sync(0xffffffffu, colsum[j][1], off);
            }
        }
        __syncthreads();                 // sat no longer read: reuse as scratch
        float* scs = sat;                // [8 warps][32]
        if (g == 0) {
            #pragma unroll
            for (int j = 0; j < 4; j++) {
                scs[w * 32 + 8 * j + 2 * t]     = colsum[j][0];
                scs[w * 32 + 8 * j + 2 * t + 1] = colsum[j][1];
            }
        }
        __syncthreads();
        if (tid < C32) {
            float s = 0.f;
            #pragma unroll
            for (int ww = 0; ww < 8; ww++) s += scs[ww * 32 + tid];
            g_sap[(b * NCHUNK + chunk) * C32 + tid] = s;
        }
    }
}

// =====================================================================
// Slot kernel: one CTA per (batch, slot). Grid = 512, 128 threads.
// All slot-level math is independent per slot; weights stay L2-hot.
// =====================================================================
__global__ void __launch_bounds__(128)
vslot_slots(const float* __restrict__ slots_in,
            const float* __restrict__ Wq,  const float* __restrict__ Wk,
            const float* __restrict__ Wv,
            const float* __restrict__ W_ih, const float* __restrict__ W_hh,
            const float* __restrict__ b_ih, const float* __restrict__ b_hh,
            const float* __restrict__ lns_g, const float* __restrict__ lns_b,
            const float* __restrict__ lnm_g, const float* __restrict__ lnm_b,
            const float* __restrict__ W1, const float* __restrict__ b1v,
            const float* __restrict__ W2, const float* __restrict__ b2v,
            float* __restrict__ out_slots, int first, int last)
{
    __shared__ float s_h[D];          // previous slot state
    __shared__ float s_sax[4][D];     // reduced S' rows c = h*8+q
    __shared__ float s_sa[4];
    __shared__ float s_upd[D];
    __shared__ float s_gx[192];
    __shared__ float s_gh[192];
    __shared__ float s_ln[D];
    __shared__ float s_hid[128];
    __shared__ float s_new[D];        // slots after GRU+MLP

    const int bq  = blockIdx.x;
    const int b   = bq >> 3;
    const int q   = bq & 7;
    const int tid = threadIdx.x;

    if (first) {
        if (tid < D) s_new[tid] = slots_in[(b * NQ + q) * D + tid];
        __syncthreads();
    } else {
        if (tid < D) s_h[tid] = g_slots[(b * NQ + q) * D + tid];
        // reduce per-chunk partials for this slot's 4 rows (c = h*8+q)
        for (int o = tid; o < 4 * D; o += 128) {
            int h = o >> 6, e = o & 63, c = h * 8 + q;
            float acc = 0.f;
            #pragma unroll
            for (int ch = 0; ch < NCHUNK; ch++)
                acc += g_part[(size_t)((b * NCHUNK + ch) * C32 + c) * D + e];
            s_sax[h][e] = acc;
        }
        if (tid < 4) {
            int c = tid * 8 + q;
            float acc = 0.f;
            #pragma unroll
            for (int ch = 0; ch < NCHUNK; ch++)
                acc += g_sap[(b * NCHUNK + ch) * C32 + c];
            s_sa[tid] = acc;
        }
        __syncthreads();

        // updates[hd] = (S'[c=h*8+q] @ Wv[:, hd]) / sa[h], hd = h*16+dh
        // 2 threads per output, 32 e each, pair-reduce via shfl
        {
            int hd = tid >> 1, half = tid & 1, h = hd >> 4;
            float acc = 0.f;
            const float* sr = s_sax[h];
            #pragma unroll
            for (int j = 0; j < 32; j++) {
                int e = half * 32 + j;
                acc = fmaf(sr[e], Wv[e * 64 + hd], acc);
            }
            acc += __shfl_xor_sync(0xffffffffu, acc, 1);
            if (half == 0) s_upd[hd] = acc / s_sa[h];
        }
        __syncthreads();

        // gates: 384 dot-64 products (192 gx + 192 gh)
        for (int o = tid; o < 384; o += 128) {
            int cc = o & 191 ? 0 : 0;  // placeholder (computed below)
            cc = (o < 192) ? o : (o - 192);
            const float* Wrow = (o < 192) ? &W_ih[cc * 64] : &W_hh[cc * 64];
            const float* xin  = (o < 192) ? s_upd : s_h;
            float acc = (o < 192) ? b_ih[cc] : b_hh[cc];
            #pragma unroll
            for (int dd = 0; dd < 64; dd++)
                acc = fmaf(xin[dd], Wrow[dd], acc);
            if (o < 192) s_gx[cc] = acc; else s_gh[cc] = acc;
        }
        __syncthreads();

        if (tid < D) {
            float r = 1.f / (1.f + __expf(-(s_gx[tid]       + s_gh[tid])));
            float z = 1.f / (1.f + __expf(-(s_gx[64 + tid]  + s_gh[64 + tid])));
            float n = tanhf(s_gx[128 + tid] + r * s_gh[128 + tid]);
            s_new[tid] = (1.f - z) * n + z * s_h[tid];
        }
        __syncthreads();

        // MLP layernorm on warp 0
        if (tid < 32) {
            float x0 = s_new[tid], x1 = s_new[tid + 32];
            float s = x0 + x1, qq = x0 * x0 + x1 * x1;
            #pragma unroll
            for (int off = 16; off; off >>= 1) {
                s  += __shfl_xor_sync(0xffffffffu, s,  off);
                qq += __shfl_xor_sync(0xffffffffu, qq, off);
            }
            float m = s * (1.f / 64.f);
            float var = qq * (1.f / 64.f) - m * m;
            float rs = rsqrtf(var + 1e-5f);
            s_ln[tid]      = (x0 - m) * rs * lnm_g[tid]      + lnm_b[tid];
            s_ln[tid + 32] = (x1 - m) * rs * lnm_g[tid + 32] + lnm_b[tid + 32];
        }
        __syncthreads();

        // hidden = relu(s_ln @ W1 + b1): 128 outputs, coalesced W1 reads
        {
            float acc = b1v[tid];
            #pragma unroll
            for (int dd = 0; dd < 64; dd++)
                acc = fmaf(s_ln[dd], W1[dd * 128 + tid], acc);
            s_hid[tid] = fmaxf(acc, 0.f);
        }
        __syncthreads();

        // out = s_new + (hid @ W2 + b2): 64 outputs, 2 threads each
        {
            int dd = tid >> 1, half = tid & 1;
            float acc = 0.f;
            #pragma unroll
            for (int j = 0; j < 64; j++) {
                int jj = half * 64 + j;
                acc = fmaf(s_hid[jj], W2[jj * 64 + dd], acc);
            }
            acc += __shfl_xor_sync(0xffffffffu, acc, 1);
            if (half == 0) s_new[dd] += acc + b2v[dd];
        }
        __syncthreads();
    }

    if (tid < D) g_slots[(b * NQ + q) * D + tid] = s_new[tid];

    if (last) {
        if (tid < D) out_slots[(b * NQ + q) * D + tid] = s_new[tid];
        return;
    }

    // pre-phase: slot LN -> qm = ln @ Wq -> Wfold columns c = h*8+q
    if (tid < 32) {
        float x0 = s_new[tid], x1 = s_new[tid + 32];
        float s = x0 + x1, qq = x0 * x0 + x1 * x1;
        #pragma unroll
        for (int off = 16; off; off >>= 1) {
            s  += __shfl_xor_sync(0xffffffffu, s,  off);
            qq += __shfl_xor_sync(0xffffffffu, qq, off);
        }
        float m = s * (1.f / 64.f);
        float var = qq * (1.f / 64.f) - m * m;
        float rs = rsqrtf(var + 1e-5f);
        s_ln[tid]      = (x0 - m) * rs * lns_g[tid]      + lns_b[tid];
        s_ln[tid + 32] = (x1 - m) * rs * lns_g[tid + 32] + lns_b[tid + 32];
    }
    __syncthreads();

    // qm[e] = s_ln @ Wq[:,e]  (reuse s_hid as qm storage; coalesced Wq)
    {
        int e = tid >> 1, half = tid & 1;
        float acc = 0.f;
        #pragma unroll
        for (int j = 0; j < 32; j++) {
            int dd = half * 32 + j;
            acc = fmaf(s_ln[dd], Wq[dd * 64 + e], acc);
        }
        acc += __shfl_xor_sync(0xffffffffu, acc, 1);
        if (half == 0) s_hid[e] = acc;
    }
    __syncthreads();

    // Wfold[c=h*8+q][e] = 0.25 * sum_{d<16} Wk[e, h*16+d] * qm[h*16+d]
    for (int o = tid; o < 4 * D; o += 128) {
        int h = o >> 6, e = o & 63, c = h * 8 + q;
        float acc = 0.f;
        #pragma unroll
        for (int dd = 0; dd < 16; dd++)
            acc = fmaf(Wk[e * 64 + h * 16 + dd], s_hid[h * 16 + dd], acc);
        g_wfold[(b * C32 + c) * D + e] = to_tf32(acc * 0.25f);
    }
}

// =====================================================================
// launcher
// =====================================================================
extern "C" void kernel_launch(void* const* d_in, const int* in_sizes, int n_in,
                              void* d_out, int out_size)
{
    const float* inputs = (const float*)d_in[0];
    const float* slots  = (const float*)d_in[1];
    const float* lnin_g = (const float*)d_in[2];
    const float* lnin_b = (const float*)d_in[3];
    const float* lns_g  = (const float*)d_in[4];
    const float* lns_b  = (const float*)d_in[5];
    const float* lnm_g  = (const float*)d_in[6];
    const float* lnm_b  = (const float*)d_in[7];
    const float* Wq     = (const float*)d_in[8];
    const float* Wk     = (const float*)d_in[9];
    const float* Wv     = (const float*)d_in[10];
    const float* W_ih   = (const float*)d_in[11];
    const float* W_hh   = (const float*)d_in[12];
    const float* b_ih   = (const float*)d_in[13];
    const float* b_hh   = (const float*)d_in[14];
    const float* W1     = (const float*)d_in[15];
    const float* b1     = (const float*)d_in[16];
    const float* W2     = (const float*)d_in[17];
    const float* b2     = (const float*)d_in[18];

    float* out       = (float*)d_out;
    float* out_slots = out;                  // [64, 8, 64]
    float* out_vis   = out + B_ * NQ * D;    // [64, 8192, 8]

    size_t smem = (size_t)(2 * TT * SX + C32 * SAT + C32 * SWF + 128) * sizeof(float);
    cudaFuncSetAttribute(vslot_main,
                         cudaFuncAttributeMaxDynamicSharedMemorySize, (int)smem);

#define SLOT_K(first, last)                                                     \
    vslot_slots<<<B_ * NQ, 128>>>(slots, Wq, Wk, Wv, W_ih, W_hh, b_ih, b_hh,     \
                             lns_g, lns_b, lnm_g, lnm_b, W1, b1, W2, b2,         \
                             out_slots, (first), (last))

    SLOT_K(1, 0);                                                        // init + Wfold0
    vslot_main<<<B_ * NCHUNK, 256, smem>>>(inputs, lnin_g, lnin_b, out_vis, 0);
    SLOT_K(0, 0);                                                        // post0 + pre1
    vslot_main<<<B_ * NCHUNK, 256, smem>>>(inputs, lnin_g, lnin_b, out_vis, 0);
    SLOT_K(0, 0);                                                        // post1 + pre2
    vslot_main<<<B_ * NCHUNK, 256, smem>>>(inputs, lnin_g, lnin_b, out_vis, 1);
    SLOT_K(0, 1);                                                        // post2 -> out
#undef SLOT_K
}

// round 5
// speedup vs baseline: 1.9916x; 1.9916x over previous
#include <cuda_runtime.h>
#include <cstdint>
#include <cstddef>

// ---------------- problem constants ----------------
#define B_     64
#define NKV    8192
#define D      64      // INPUT_SIZE == SLOT_SIZE
#define NQ     8
#define C32    32      // NUM_HEADS * NUM_SLOTS
#define EPS_A  1e-8f
#define NCHUNK 32
#define TPC    256     // tokens per CTA
#define TT     64      // tokens per tile
#define NTILES (TPC / TT)   // 4

#define SX  68         // smem row stride for lnX tile [64][SX]
#define SAT 68         // smem row stride for attn^T   [32][SAT]
#define SWF 68         // smem row stride for Wfold    [32][SWF]

// ---------------- device scratch (no allocs allowed) ----------------
__device__ float g_wfold[B_ * C32 * D];              // [b][c][e], tf32-rounded
__device__ float g_part [B_ * NCHUNK * C32 * D];     // per-chunk S' partials
__device__ float g_sap  [B_ * NCHUNK * C32];         // per-chunk column-sum partials
__device__ float g_slots[B_ * NQ * D];               // working slots

// ---------------- helpers ----------------
__device__ __forceinline__ float to_tf32(float x) {
    uint32_t u;
    asm("cvt.rna.tf32.f32 %0, %1;" : "=r"(u) : "f"(x));
    return __uint_as_float(u);
}
__device__ __forceinline__ uint32_t f2u(float x) { return __float_as_uint(x); }

__device__ __forceinline__ void mma8(float c[4],
                                     uint32_t a0, uint32_t a1, uint32_t a2, uint32_t a3,
                                     uint32_t b0, uint32_t b1) {
    asm volatile(
        "mma.sync.aligned.m16n8k8.row.col.f32.tf32.tf32.f32 "
        "{%0,%1,%2,%3},{%4,%5,%6,%7},{%8,%9},{%0,%1,%2,%3};"
        : "+f"(c[0]), "+f"(c[1]), "+f"(c[2]), "+f"(c[3])
        : "r"(a0), "r"(a1), "r"(a2), "r"(a3), "r"(b0), "r"(b1));
}

__device__ __forceinline__ void cp_async16(uint32_t smem_addr, const void* gptr) {
    asm volatile("cp.async.cg.shared.global [%0], [%1], 16;"
                 :: "r"(smem_addr), "l"(gptr));
}
__device__ __forceinline__ void cp_commit() {
    asm volatile("cp.async.commit_group;");
}
__device__ __forceinline__ void cp_wait0() {
    asm volatile("cp.async.wait_group 0;");
}

// =====================================================================
// Main fused streaming kernel: one CTA per (batch, 256-token chunk),
// four 64-token tiles, cp.async double-buffered, 128 threads, 4 CTAs/SM.
// Per tile: LN in mma-A-fragment register layout -> GEMM1 (tensor) ->
// softmax-32 in regs (+vis on last iter) -> attn^T to smem ->
// GEMM2 S' += attn^T @ lnX (tensor).
// =====================================================================
__global__ void __launch_bounds__(128, 4)
vslot_main(const float* __restrict__ inputs,
           const float* __restrict__ lng_g,
           const float* __restrict__ lnb_g,
           float* __restrict__ vis,
           int last)
{
    extern __shared__ float sm[];
    float* sx0  = sm;                      // [64][SX] tile buffer 0
    float* sx1  = sx0 + TT * SX;           // [64][SX] tile buffer 1
    float* sat  = sx1 + TT * SX;           // [32][SAT] (attn+eps)^T (tf32)
    float* swf  = sat + C32 * SAT;         // [32][SWF] Wfold[c][e]
    float* slng = swf + C32 * SWF;         // [64]
    float* slnb = slng + 64;               // [64]

    const int b     = blockIdx.x >> 5;
    const int chunk = blockIdx.x & 31;
    const int n0    = chunk * TPC;
    const int tid   = threadIdx.x;
    const int w     = tid >> 5;       // 0..3
    const int lane  = tid & 31;
    const int g     = lane >> 2;      // 0..7
    const int t     = lane & 3;       // 0..3
    const int r0    = w * 16 + g;     // this thread's mma rows: r0, r0+8 (0..63)

    for (int i = tid; i < C32 * D; i += 128)
        swf[(i >> 6) * SWF + (i & 63)] = g_wfold[b * C32 * D + i];
    if (tid < 64) { slng[tid] = lng_g[tid]; slnb[tid] = lnb_g[tid]; }

    const float4* gbase = reinterpret_cast<const float4*>(
        inputs + ((size_t)b * NKV + n0) * D);
    uint32_t sxa[2];
    sxa[0] = (uint32_t)__cvta_generic_to_shared(sx0);
    sxa[1] = (uint32_t)__cvta_generic_to_shared(sx1);

    // prologue: prefetch tile 0 (64 tokens x 64 f32 = 1024 float4)
    #pragma unroll
    for (int k = 0; k < 8; k++) {
        int i = tid + 128 * k;
        cp_async16(sxa[0] + ((i >> 4) * SX + (i & 15) * 4) * 4, gbase + i);
    }
    cp_commit();

    float c2[4][4];        // GEMM2 accumulators (32 cols per warp, persist)
    float colsum[4][2];    // per-owned-column (attn+eps) sums
    #pragma unroll
    for (int a = 0; a < 4; a++)
        #pragma unroll
        for (int i = 0; i < 4; i++) c2[a][i] = 0.f;
    #pragma unroll
    for (int a = 0; a < 4; a++) { colsum[a][0] = 0.f; colsum[a][1] = 0.f; }

    #pragma unroll
    for (int t4 = 0; t4 < NTILES; t4++) {
        float* sx = (t4 & 1) ? sx1 : sx0;

        cp_wait0();
        __syncthreads();   // tile t4 visible; all warps done with buf(t4^1)

        if (t4 + 1 < NTILES) {   // prefetch next tile
            const float4* gn = gbase + (size_t)(t4 + 1) * (TT * D / 4);
            uint32_t dst = sxa[(t4 + 1) & 1];
            #pragma unroll
            for (int k = 0; k < 8; k++) {
                int i = tid + 128 * k;
                cp_async16(dst + ((i >> 4) * SX + (i & 15) * 4) * 4, gn + i);
            }
            cp_commit();
        }

        // ---- layernorm in A-fragment layout: rows r0, r0+8, cols 4j+t ----
        float v0[16], v1[16];
        float s0 = 0.f, q0 = 0.f, s1 = 0.f, q1 = 0.f;
        {
            const float* p0 = &sx[r0 * SX + t];
            const float* p1 = &sx[(r0 + 8) * SX + t];
            #pragma unroll
            for (int j = 0; j < 16; j++) {
                float x0 = p0[4 * j], x1 = p1[4 * j];
                v0[j] = x0; v1[j] = x1;
                s0 += x0; q0 = fmaf(x0, x0, q0);
                s1 += x1; q1 = fmaf(x1, x1, q1);
            }
            s0 += __shfl_xor_sync(0xffffffffu, s0, 1);
            q0 += __shfl_xor_sync(0xffffffffu, q0, 1);
            s1 += __shfl_xor_sync(0xffffffffu, s1, 1);
            q1 += __shfl_xor_sync(0xffffffffu, q1, 1);
            s0 += __shfl_xor_sync(0xffffffffu, s0, 2);
            q0 += __shfl_xor_sync(0xffffffffu, q0, 2);
            s1 += __shfl_xor_sync(0xffffffffu, s1, 2);
            q1 += __shfl_xor_sync(0xffffffffu, q1, 2);
            float m0 = s0 * (1.f / 64.f);
            float m1 = s1 * (1.f / 64.f);
            float rs0 = rsqrtf(fmaf(-m0, m0, q0 * (1.f / 64.f)) + 1e-5f);
            float rs1 = rsqrtf(fmaf(-m1, m1, q1 * (1.f / 64.f)) + 1e-5f);
            float* o0 = &sx[r0 * SX + t];
            float* o1 = &sx[(r0 + 8) * SX + t];
            #pragma unroll
            for (int j = 0; j < 16; j++) {
                float gg = slng[4 * j + t], bb = slnb[4 * j + t];
                v0[j] = to_tf32(fmaf((v0[j] - m0) * rs0, gg, bb));
                v1[j] = to_tf32(fmaf((v1[j] - m1) * rs1, gg, bb));
                o0[4 * j] = v0[j];
                o1[4 * j] = v1[j];
            }
        }

        // ---- GEMM1: logits[64,32] = lnX @ Wfold, A from registers ----
        float c1[4][4];
        #pragma unroll
        for (int j = 0; j < 4; j++)
            #pragma unroll
            for (int i = 0; i < 4; i++) c1[j][i] = 0.f;
        #pragma unroll
        for (int ks = 0; ks < 8; ks++) {
            uint32_t a0 = f2u(v0[2 * ks]);
            uint32_t a1 = f2u(v1[2 * ks]);
            uint32_t a2 = f2u(v0[2 * ks + 1]);
            uint32_t a3 = f2u(v1[2 * ks + 1]);
            #pragma unroll
            for (int j = 0; j < 4; j++) {
                const float* bp = &swf[(8 * j + g) * SWF + 8 * ks + t];
                mma8(c1[j], a0, a1, a2, a3, f2u(bp[0]), f2u(bp[4]));
            }
        }

        // ---- softmax over 32 cols for rows r0, r0+8 ----
        float m0 = -1e30f, m1 = -1e30f;
        #pragma unroll
        for (int j = 0; j < 4; j++) {
            m0 = fmaxf(m0, fmaxf(c1[j][0], c1[j][1]));
            m1 = fmaxf(m1, fmaxf(c1[j][2], c1[j][3]));
        }
        m0 = fmaxf(m0, __shfl_xor_sync(0xffffffffu, m0, 1));
        m0 = fmaxf(m0, __shfl_xor_sync(0xffffffffu, m0, 2));
        m1 = fmaxf(m1, __shfl_xor_sync(0xffffffffu, m1, 1));
        m1 = fmaxf(m1, __shfl_xor_sync(0xffffffffu, m1, 2));
        float ss0 = 0.f, ss1 = 0.f;
        #pragma unroll
        for (int j = 0; j < 4; j++) {
            c1[j][0] = __expf(c1[j][0] - m0);
            c1[j][1] = __expf(c1[j][1] - m0);
            c1[j][2] = __expf(c1[j][2] - m1);
            c1[j][3] = __expf(c1[j][3] - m1);
            ss0 += c1[j][0] + c1[j][1];
            ss1 += c1[j][2] + c1[j][3];
        }
        ss0 += __shfl_xor_sync(0xffffffffu, ss0, 1);
        ss0 += __shfl_xor_sync(0xffffffffu, ss0, 2);
        ss1 += __shfl_xor_sync(0xffffffffu, ss1, 1);
        ss1 += __shfl_xor_sync(0xffffffffu, ss1, 2);
        float inv0 = 1.f / ss0, inv1 = 1.f / ss1;

        if (last) {   // attn_vis[b,n,q] = sum_h attn[n, h*8+q]
            float w00 = 0.f, w01 = 0.f, w10 = 0.f, w11 = 0.f;
            #pragma unroll
            for (int j = 0; j < 4; j++) {
                w00 += c1[j][0]; w01 += c1[j][1];
                w10 += c1[j][2]; w11 += c1[j][3];
            }
            size_t nrow = (size_t)b * NKV + n0 + t4 * TT;
            *reinterpret_cast<float2*>(&vis[(nrow + r0) * NQ + 2 * t])
                = make_float2(w00 * inv0, w01 * inv0);
            *reinterpret_cast<float2*>(&vis[(nrow + r0 + 8) * NQ + 2 * t])
                = make_float2(w10 * inv1, w11 * inv1);
        }

        // ---- attn+eps -> sat (transposed, tf32) + column sums ----
        #pragma unroll
        for (int j = 0; j < 4; j++) {
            int cc = 8 * j + 2 * t;
            float a00 = fmaf(c1[j][0], inv0, EPS_A);
            float a01 = fmaf(c1[j][1], inv0, EPS_A);
            float a10 = fmaf(c1[j][2], inv1, EPS_A);
            float a11 = fmaf(c1[j][3], inv1, EPS_A);
            sat[cc * SAT + r0]           = to_tf32(a00);
            sat[(cc + 1) * SAT + r0]     = to_tf32(a01);
            sat[cc * SAT + r0 + 8]       = to_tf32(a10);
            sat[(cc + 1) * SAT + r0 + 8] = to_tf32(a11);
            colsum[j][0] += a00 + a10;
            colsum[j][1] += a01 + a11;
        }
        __syncthreads();   // sat + tf32 lnX visible to all warps

        // ---- GEMM2: S'[32,64] += (attn+eps)^T[32,64] @ lnX[64,64] ----
        {
            const int mblk = w & 1;           // 0..1  (rows 16*mblk..+15)
            const int ncol = (w >> 1) * 32;   // 32 output cols per warp
            const float* atp = &sat[(16 * mblk + g) * SAT];
            #pragma unroll
            for (int ks = 0; ks < 8; ks++) {
                int kb = 8 * ks;
                uint32_t a0 = f2u(atp[kb + t]);
                uint32_t a1 = f2u(atp[8 * SAT + kb + t]);
                uint32_t a2 = f2u(atp[kb + t + 4]);
                uint32_t a3 = f2u(atp[8 * SAT + kb + t + 4]);
                #pragma unroll
                for (int nb = 0; nb < 4; nb++) {
                    const float* bp = &sx[(kb + t) * SX + ncol + 8 * nb + g];
                    mma8(c2[nb], a0, a1, a2, a3, f2u(bp[0]), f2u(bp[4 * SX]));
                }
            }
        }
    }

    // ---- epilogue: deterministic per-chunk partials ----
    {
        const int mblk = w & 1;
        const int ncol = (w >> 1) * 32;
        const int crow = 16 * mblk + g;
        float* pp = &g_part[(size_t)(b * NCHUNK + chunk) * C32 * D];
        #pragma unroll
        for (int nb = 0; nb < 4; nb++) {
            int e0 = ncol + 8 * nb + 2 * t;
            pp[crow * D + e0]           = c2[nb][0];
            pp[crow * D + e0 + 1]       = c2[nb][1];
            pp[(crow + 8) * D + e0]     = c2[nb][2];
            pp[(crow + 8) * D + e0 + 1] = c2[nb][3];
        }
        #pragma unroll
        for (int off = 4; off < 32; off <<= 1) {
            #pragma unroll
            for (int j = 0; j < 4; j++) {
                colsum[j][0] += __shfl_xor_sync(0xffffffffu, colsum[j][0], off);
                colsum[j][1] += __shfl_xor_sync(0xffffffffu, colsum[j][1], off);
            }
        }
        __syncthreads();                 // sat no longer read: reuse as scratch
        float* scs = sat;                // [4 warps][32]
        if (g == 0) {
            #pragma unroll
            for (int j = 0; j < 4; j++) {
                scs[w * 32 + 8 * j + 2 * t]     = colsum[j][0];
                scs[w * 32 + 8 * j + 2 * t + 1] = colsum[j][1];
            }
        }
        __syncthreads();
        if (tid < C32) {
            float s = 0.f;
            #pragma unroll
            for (int ww = 0; ww < 4; ww++) s += scs[ww * 32 + tid];
            g_sap[(b * NCHUNK + chunk) * C32 + tid] = s;
        }
    }
}

// =====================================================================
// Per-batch slot kernel (R2 structure, proven ~33us). Improvements:
// both gate-weight matrices staged concurrently in one phase; gx and gh
// computed in a single fused phase (2 fewer barriers).
// =====================================================================
__global__ void __launch_bounds__(256)
vslot_slots(const float* __restrict__ slots_in,
            const float* __restrict__ Wq,  const float* __restrict__ Wk,
            const float* __restrict__ Wv,
            const float* __restrict__ W_ih, const float* __restrict__ W_hh,
            const float* __restrict__ b_ih, const float* __restrict__ b_hh,
            const float* __restrict__ lns_g, const float* __restrict__ lns_b,
            const float* __restrict__ lnm_g, const float* __restrict__ lnm_b,
            const float* __restrict__ W1, const float* __restrict__ b1v,
            const float* __restrict__ W2, const float* __restrict__ b2v,
            float* __restrict__ out_slots, int first, int last)
{
    extern __shared__ float wbuf[];     // [192][65] W_ih | [192][65] W_hh
    float* wih = wbuf;
    float* whh = wbuf + 192 * 65;
    __shared__ float s_slots[NQ][D];
    __shared__ float s_upd[NQ][D];
    __shared__ float s_gx[NQ][192];
    __shared__ float s_gh[NQ][192];
    __shared__ float s_ln[NQ][D];
    __shared__ float s_hid[NQ][128];
    __shared__ float s_sax[C32][D];
    __shared__ float s_sa[C32];

    const int b = blockIdx.x;
    const int tid = threadIdx.x;

    if (first) {
        for (int i = tid; i < NQ * D; i += 256)
            (&s_slots[0][0])[i] = slots_in[b * NQ * D + i];
        __syncthreads();
    } else {
        // reduce the chunk partials (fixed order -> deterministic)
        for (int i = tid; i < C32 * D; i += 256) {
            float acc = 0.f;
            #pragma unroll
            for (int ch = 0; ch < NCHUNK; ch++)
                acc += g_part[(size_t)(b * NCHUNK + ch) * C32 * D + i];
            (&s_sax[0][0])[i] = acc;
        }
        if (tid < C32) {
            float acc = 0.f;
            #pragma unroll
            for (int ch = 0; ch < NCHUNK; ch++)
                acc += g_sap[(b * NCHUNK + ch) * C32 + tid];
            s_sa[tid] = acc;
        }
        for (int i = tid; i < NQ * D; i += 256)
            (&s_slots[0][0])[i] = g_slots[b * NQ * D + i];
        // stage both gate-weight matrices concurrently (coalesced)
        for (int i = tid; i < 192 * 64; i += 256) {
            wih[(i >> 6) * 65 + (i & 63)] = W_ih[i];
            whh[(i >> 6) * 65 + (i & 63)] = W_hh[i];
        }
        __syncthreads();

        // updates[q, h*16+dh] = (S'[c] @ Wv[:, h*16+dh]) / sa[c],  c = h*8+q
        for (int o = tid; o < NQ * D; o += 256) {
            int q = o >> 6, hd = o & 63, h = hd >> 4, c = h * 8 + q;
            float acc = 0.f;
            #pragma unroll
            for (int e = 0; e < 64; e++)
                acc = fmaf(s_sax[c][e], Wv[e * 64 + hd], acc);
            s_upd[q][hd] = acc / s_sa[c];
        }
        __syncthreads();

        // gx = upd @ W_ih^T + b_ih AND gh = h @ W_hh^T + b_hh, one phase
        for (int o = tid; o < NQ * 192; o += 256) {
            int q = o / 192, cc = o % 192;
            float gx = b_ih[cc], gh = b_hh[cc];
            const float* wr = &wih[cc * 65];
            const float* wh = &whh[cc * 65];
            #pragma unroll
            for (int dd = 0; dd < 64; dd++) {
                gx = fmaf(s_upd[q][dd],   wr[dd], gx);
                gh = fmaf(s_slots[q][dd], wh[dd], gh);
            }
            s_gx[q][cc] = gx;
            s_gh[q][cc] = gh;
        }
        __syncthreads();

        for (int o = tid; o < NQ * D; o += 256) {
            int q = o >> 6, dd = o & 63;
            float r = 1.f / (1.f + __expf(-(s_gx[q][dd]       + s_gh[q][dd])));
            float z = 1.f / (1.f + __expf(-(s_gx[q][64 + dd]  + s_gh[q][64 + dd])));
            float n = tanhf(s_gx[q][128 + dd] + r * s_gh[q][128 + dd]);
            s_upd[q][dd] = (1.f - z) * n + z * s_slots[q][dd];  // new slots
        }
        __syncthreads();

        // MLP layernorm (warp per slot)
        {
            int w = tid >> 5, lane = tid & 31;
            float x0 = s_upd[w][lane], x1 = s_upd[w][lane + 32];
            float s = x0 + x1, qq = x0 * x0 + x1 * x1;
            #pragma unroll
            for (int off = 16; off; off >>= 1) {
                s  += __shfl_xor_sync(0xffffffffu, s,  off);
                qq += __shfl_xor_sync(0xffffffffu, qq, off);
            }
            float m = s * (1.f / 64.f);
            float var = qq * (1.f / 64.f) - m * m;
            float rs = rsqrtf(var + 1e-5f);
            s_ln[w][lane]      = (x0 - m) * rs * lnm_g[lane]      + lnm_b[lane];
            s_ln[w][lane + 32] = (x1 - m) * rs * lnm_g[lane + 32] + lnm_b[lane + 32];
        }
        __syncthreads();

        for (int o = tid; o < NQ * 128; o += 256) {   // W1 reads coalesced
            int q = o >> 7, j = o & 127;
            float acc = b1v[j];
            #pragma unroll
            for (int dd = 0; dd < 64; dd++)
                acc = fmaf(s_ln[q][dd], W1[dd * 128 + j], acc);
            s_hid[q][j] = fmaxf(acc, 0.f);
        }
        __syncthreads();

        for (int o = tid; o < NQ * D; o += 256) {     // W2 reads coalesced
            int q = o >> 6, dd = o & 63;
            float acc = b2v[dd];
            #pragma unroll
            for (int j = 0; j < 128; j++)
                acc = fmaf(s_hid[q][j], W2[j * 64 + dd], acc);
            s_slots[q][dd] = s_upd[q][dd] + acc;
        }
        __syncthreads();
    }

    for (int i = tid; i < NQ * D; i += 256)
        g_slots[b * NQ * D + i] = (&s_slots[0][0])[i];

    if (last) {
        for (int i = tid; i < NQ * D; i += 256)
            out_slots[b * NQ * D + i] = (&s_slots[0][0])[i];
    } else {
        // pre-phase: slot LN -> q = ln(slots) @ Wq -> Wfold (tf32)
        {
            int w = tid >> 5, lane = tid & 31;
            float x0 = s_slots[w][lane], x1 = s_slots[w][lane + 32];
            float s = x0 + x1, qq = x0 * x0 + x1 * x1;
            #pragma unroll
            for (int off = 16; off; off >>= 1) {
                s  += __shfl_xor_sync(0xffffffffu, s,  off);
                qq += __shfl_xor_sync(0xffffffffu, qq, off);
            }
            float m = s * (1.f / 64.f);
            float var = qq * (1.f / 64.f) - m * m;
            float rs = rsqrtf(var + 1e-5f);
            s_ln[w][lane]      = (x0 - m) * rs * lns_g[lane]      + lns_b[lane];
            s_ln[w][lane + 32] = (x1 - m) * rs * lns_g[lane + 32] + lns_b[lane + 32];
        }
        __syncthreads();

        for (int o = tid; o < NQ * D; o += 256) {   // qm = s_ln @ Wq (coalesced)
            int q = o >> 6, e = o & 63;
            float acc = 0.f;
            #pragma unroll
            for (int dd = 0; dd < 64; dd++)
                acc = fmaf(s_ln[q][dd], Wq[dd * 64 + e], acc);
            s_upd[q][e] = acc;
        }
        __syncthreads();

        // Wfold[e, c=(h*8+q)] = 0.25 * sum_{d<16} Wk[e, h*16+d] * qm[q, h*16+d]
        for (int o = tid; o < C32 * D; o += 256) {
            int c = o >> 6, e = o & 63, h = c >> 3, q = c & 7;
            float acc = 0.f;
            #pragma unroll
            for (int dd = 0; dd < 16; dd++)
                acc = fmaf(Wk[e * 64 + h * 16 + dd], s_upd[q][h * 16 + dd], acc);
            g_wfold[b * C32 * D + c * 64 + e] = to_tf32(acc * 0.25f);
        }
    }
}

// =====================================================================
// launcher
// =====================================================================
extern "C" void kernel_launch(void* const* d_in, const int* in_sizes, int n_in,
                              void* d_out, int out_size)
{
    const float* inputs = (const float*)d_in[0];
    const float* slots  = (const float*)d_in[1];
    const float* lnin_g = (const float*)d_in[2];
    const float* lnin_b = (const float*)d_in[3];
    const float* lns_g  = (const float*)d_in[4];
    const float* lns_b  = (const float*)d_in[5];
    const float* lnm_g  = (const float*)d_in[6];
    const float* lnm_b  = (const float*)d_in[7];
    const float* Wq     = (const float*)d_in[8];
    const float* Wk     = (const float*)d_in[9];
    const float* Wv     = (const float*)d_in[10];
    const float* W_ih   = (const float*)d_in[11];
    const float* W_hh   = (const float*)d_in[12];
    const float* b_ih   = (const float*)d_in[13];
    const float* b_hh   = (const float*)d_in[14];
    const float* W1     = (const float*)d_in[15];
    const float* b1     = (const float*)d_in[16];
    const float* W2     = (const float*)d_in[17];
    const float* b2     = (const float*)d_in[18];

    float* out       = (float*)d_out;
    float* out_slots = out;                  // [64, 8, 64]
    float* out_vis   = out + B_ * NQ * D;    // [64, 8192, 8]

    size_t smem = (size_t)(2 * TT * SX + C32 * SAT + C32 * SWF + 128) * sizeof(float);
    cudaFuncSetAttribute(vslot_main,
                         cudaFuncAttributeMaxDynamicSharedMemorySize, (int)smem);
    size_t smem_s = (size_t)(2 * 192 * 65) * sizeof(float);
    cudaFuncSetAttribute(vslot_slots,
                         cudaFuncAttributeMaxDynamicSharedMemorySize, (int)smem_s);

#define SLOT_K(first, last)                                                     \
    vslot_slots<<<B_, 256, smem_s>>>(slots, Wq, Wk, Wv, W_ih, W_hh, b_ih, b_hh,  \
                             lns_g, lns_b, lnm_g, lnm_b, W1, b1, W2, b2,         \
                             out_slots, (first), (last))

    SLOT_K(1, 0);                                                        // init + Wfold0
    vslot_main<<<B_ * NCHUNK, 128, smem>>>(inputs, lnin_g, lnin_b, out_vis, 0);
    SLOT_K(0, 0);                                                        // post0 + pre1
    vslot_main<<<B_ * NCHUNK, 128, smem>>>(inputs, lnin_g, lnin_b, out_vis, 0);
    SLOT_K(0, 0);                                                        // post1 + pre2
    vslot_main<<<B_ * NCHUNK, 128, smem>>>(inputs, lnin_g, lnin_b, out_vis, 1);
    SLOT_K(0, 1);                                                        // post2 -> out
#undef SLOT_K
}